// round 3
// baseline (speedup 1.0000x reference)
#include <cuda_runtime.h>
#include <cstddef>
#include <cstdint>

#define NN 20000
#define NE 200000
#define NG 128

// ---------------- scratch (device globals) ----------------------------------
__device__ float g_n1[(size_t)NN * 256];
__device__ float g_e1[(size_t)NE * 256];
__device__ float g_g1[(size_t)NG * 256];
__device__ float g_emid[(size_t)NE * 256];
__device__ float g_nin[(size_t)NN * 768];
__device__ float g_nmid[(size_t)NN * 256];
__device__ float g_gin[(size_t)NG * 768];
__device__ float g_gmid[(size_t)NG * 256];
__device__ float g_e2n[(size_t)NN * 256];
// e2g[32768] | n2g[32768] | ncnt[20000] | gcnt_e[128] | gcnt_n[128]
#define OFF_E2G 0
#define OFF_N2G 32768
#define OFF_NCNT 65536
#define OFF_GCE 85536
#define OFF_GCN 85664
#define SMALL_N 85792
__device__ float g_small[SMALL_N];
__device__ float g_wr[1048576];   // all 9 weights, tf32-rounded

__device__ __forceinline__ float ssp(float x) {
    return fmaxf(x, 0.0f) + log1pf(__expf(-fabsf(x))) - 0.69314718055994531f;
}
__device__ __forceinline__ uint32_t f2tf32(float f) {
    uint32_t r;
    asm("cvt.rna.tf32.f32 %0, %1;" : "=r"(r) : "f"(f));
    return r;
}
__device__ __forceinline__ float rtf(float f) {
    return __uint_as_float(f2tf32(f));
}
__device__ __forceinline__ void mma_tf32(float* c,
    uint32_t a0, uint32_t a1, uint32_t a2, uint32_t a3,
    uint32_t b0, uint32_t b1)
{
    asm volatile(
        "mma.sync.aligned.m16n8k8.row.col.f32.tf32.tf32.f32 "
        "{%0,%1,%2,%3},{%4,%5,%6,%7},{%8,%9},{%0,%1,%2,%3};\n"
        : "+f"(c[0]), "+f"(c[1]), "+f"(c[2]), "+f"(c[3])
        : "r"(a0), "r"(a1), "r"(a2), "r"(a3), "r"(b0), "r"(b1));
}
__device__ __forceinline__ void cp16(uint32_t saddr, const void* g) {
    asm volatile("cp.async.cg.shared.global [%0], [%1], 16;\n"
                 :: "r"(saddr), "l"(g));
}

// ---------------- zero fill --------------------------------------------------
__global__ void zero_kernel(float* __restrict__ p, int n) {
    int i = blockIdx.x * blockDim.x + threadIdx.x;
    if (i < n) p[i] = 0.0f;
}

// ---------------- round all weights into g_wr --------------------------------
struct WSrc { const float* p[9]; };
// float offsets: n1,e1,g1, emlp, nmlp, gmlp, n2, e2, g2
#define WO0 0
#define WO1 65536
#define WO2 131072
#define WO3 196608
#define WO4 458752
#define WO5 655360
#define WO6 851968
#define WO7 917504
#define WO8 983040
__global__ __launch_bounds__(256) void round_weights(WSrc ws) {
    int f = (blockIdx.x * 256 + threadIdx.x) * 4;
    if (f >= 1048576) return;
    const float* sp; int base;
    if      (f < WO1) { sp = ws.p[0]; base = WO0; }
    else if (f < WO2) { sp = ws.p[1]; base = WO1; }
    else if (f < WO3) { sp = ws.p[2]; base = WO2; }
    else if (f < WO4) { sp = ws.p[3]; base = WO3; }
    else if (f < WO5) { sp = ws.p[4]; base = WO4; }
    else if (f < WO6) { sp = ws.p[5]; base = WO5; }
    else if (f < WO7) { sp = ws.p[6]; base = WO6; }
    else if (f < WO8) { sp = ws.p[7]; base = WO7; }
    else              { sp = ws.p[8]; base = WO8; }
    float4 v = *(const float4*)(sp + (f - base));
    v.x = rtf(v.x); v.y = rtf(v.y); v.z = rtf(v.z); v.w = rtf(v.w);
    *(float4*)(g_wr + f) = v;
}

// ---------------- main GEMM: C[M,256] = ssp(A @ W^T) variants ----------------
// Block 128x256xK, warp tile 64x64 (warps 2m x 4n), TBK=16, XOR-swizzled smem,
// cp.async double buffer. MODE1 = fused edge gather. SC1 = edge scatter fused,
// SC2 = node scatter fused. ROUND = store tf32-rounded. ADD = +R residual.
#define SMSTG 6144   // floats per stage: A[128*16] + W[256*16]

template <int MODE, int ADD, int ROUND, int SC>
__global__ __launch_bounds__(256) void gemm_k(
    const float* __restrict__ A, const float* __restrict__ W,
    const float* __restrict__ R, float* __restrict__ C,
    int M, int K,
    const int* __restrict__ src, const int* __restrict__ dst,
    const int* __restrict__ batch)
{
    __shared__ float sm[2 * SMSTG];
    const int tid = threadIdx.x;
    const int m0 = blockIdx.x * 128;

    // ---- loader setup
    const int arow = tid >> 1;
    const int ak0 = (tid & 1) * 8;
    const int sa = ((arow >> 1) & 3) * 4;
    const int sw = ((tid >> 1) & 3) * 4;
    uint32_t smb = (uint32_t)__cvta_generic_to_shared(sm);
    uint32_t aD0 = smb + (uint32_t)(arow * 16 + (ak0 ^ sa)) * 4u;
    uint32_t aD1 = smb + (uint32_t)(arow * 16 + ((ak0 + 4) ^ sa)) * 4u;
    uint32_t wD0 = smb + (uint32_t)(2048 + tid * 16 + (0 ^ sw)) * 4u;
    uint32_t wD1 = smb + (uint32_t)(2048 + tid * 16 + (4 ^ sw)) * 4u;
    uint32_t wD2 = smb + (uint32_t)(2048 + tid * 16 + (8 ^ sw)) * 4u;
    uint32_t wD3 = smb + (uint32_t)(2048 + tid * 16 + (12 ^ sw)) * 4u;
    const float* wSrc = W + (size_t)tid * K;

    const float* aSrc = nullptr;
    const float* gp0 = nullptr; const float* gp1 = nullptr;
    const float* gp2 = nullptr; const float* gp3 = nullptr;
    if (MODE == 0) {
        int r = min(m0 + arow, M - 1);
        aSrc = A + (size_t)r * K + ak0;
    } else {
        int e = min(m0 + arow, NE - 1);
        int s_ = src[e], d_ = dst[e], b_ = batch[s_];
        gp0 = g_n1 + (size_t)s_ * 256 + ak0;
        gp1 = g_n1 + (size_t)d_ * 256 + ak0;
        gp2 = g_e1 + (size_t)e * 256 + ak0;
        gp3 = g_g1 + (size_t)b_ * 256 + ak0;
    }

    auto load_tile = [&](int kt, int stg) {
        uint32_t so = (uint32_t)stg * (SMSTG * 4);
        const float* ap;
        if (MODE == 0) {
            ap = aSrc + kt * 16;
        } else {
            int sg = kt >> 4;
            const float* b = (sg == 0) ? gp0 : (sg == 1) ? gp1
                           : (sg == 2) ? gp2 : gp3;
            ap = b + (kt & 15) * 16;
        }
        cp16(aD0 + so, ap);
        cp16(aD1 + so, ap + 4);
        const float* wp = wSrc + kt * 16;
        cp16(wD0 + so, wp);
        cp16(wD1 + so, wp + 4);
        cp16(wD2 + so, wp + 8);
        cp16(wD3 + so, wp + 12);
        asm volatile("cp.async.commit_group;\n" ::: "memory");
    };

    // ---- compute setup
    const int lane = tid & 31, warp = tid >> 5;
    const int wm = (warp & 1) * 64, wn = (warp >> 1) * 64;
    const int gid = lane >> 2, tig = lane & 3;
    const int s = (gid >> 1) * 4;
    int cj[4];
#pragma unroll
    for (int j = 0; j < 4; j++) cj[j] = tig + ((4 * j) ^ s);
    const float* aF = sm + (wm + gid) * 16;
    const float* wF = sm + 2048 + (wn + gid) * 16;

    float acc[4][8][4];
#pragma unroll
    for (int mt = 0; mt < 4; mt++)
#pragma unroll
        for (int nt = 0; nt < 8; nt++)
#pragma unroll
            for (int i = 0; i < 4; i++) acc[mt][nt][i] = 0.0f;

    const int KT = K / 16;
    load_tile(0, 0);

    for (int kt = 0; kt < KT; kt++) {
        asm volatile("cp.async.wait_group 0;\n" ::: "memory");
        __syncthreads();
        if (kt + 1 < KT) load_tile(kt + 1, (kt + 1) & 1);
        const int off = (kt & 1) * SMSTG;

#pragma unroll
        for (int ks = 0; ks < 2; ks++) {
            const int j0 = ks * 2, j1 = ks * 2 + 1;
            uint32_t b0[8], b1[8];
#pragma unroll
            for (int nt = 0; nt < 8; nt++) {
                b0[nt] = __float_as_uint(wF[off + nt * 128 + cj[j0]]);
                b1[nt] = __float_as_uint(wF[off + nt * 128 + cj[j1]]);
            }
#pragma unroll
            for (int mt = 0; mt < 4; mt++) {
                uint32_t a0 = __float_as_uint(aF[off + mt * 256 + cj[j0]]);
                uint32_t a1 = __float_as_uint(aF[off + mt * 256 + 128 + cj[j0]]);
                uint32_t a2 = __float_as_uint(aF[off + mt * 256 + cj[j1]]);
                uint32_t a3 = __float_as_uint(aF[off + mt * 256 + 128 + cj[j1]]);
#pragma unroll
                for (int nt = 0; nt < 8; nt++)
                    mma_tf32(acc[mt][nt], a0, a1, a2, a3, b0[nt], b1[nt]);
            }
        }
        __syncthreads();
    }

    // ---- epilogue
    int* sdst = (int*)sm;
    int* sb = ((int*)sm) + 128;
    if (SC == 1) {
        if (tid < 128) {
            int e = min(m0 + tid, M - 1);
            sdst[tid] = dst[e];
            sb[tid] = batch[src[e]];
        }
        __syncthreads();
    } else if (SC == 2) {
        if (tid < 128) sb[tid] = batch[min(m0 + tid, M - 1)];
        __syncthreads();
    }

#pragma unroll
    for (int mt = 0; mt < 4; mt++) {
#pragma unroll
        for (int half = 0; half < 2; half++) {
            int r = wm + mt * 16 + gid + half * 8;
            int gr = m0 + r;
            if (gr >= M) continue;
#pragma unroll
            for (int nt = 0; nt < 8; nt++) {
                int c = wn + nt * 8 + tig * 2;
                float o0 = ssp(acc[mt][nt][half * 2 + 0]);
                float o1 = ssp(acc[mt][nt][half * 2 + 1]);
                if (SC == 1) {
                    atomicAdd(&g_e2n[(size_t)sdst[r] * 256 + c], o0);
                    atomicAdd(&g_e2n[(size_t)sdst[r] * 256 + c + 1], o1);
                    atomicAdd(&g_small[OFF_E2G + sb[r] * 256 + c], o0);
                    atomicAdd(&g_small[OFF_E2G + sb[r] * 256 + c + 1], o1);
                } else if (SC == 2) {
                    atomicAdd(&g_small[OFF_N2G + sb[r] * 256 + c], o0);
                    atomicAdd(&g_small[OFF_N2G + sb[r] * 256 + c + 1], o1);
                }
                if (ADD) {
                    float2 rv = *(const float2*)&R[(size_t)gr * 256 + c];
                    o0 += rv.x; o1 += rv.y;
                }
                if (ROUND) { o0 = rtf(o0); o1 = rtf(o1); }
                *(float2*)&C[(size_t)gr * 256 + c] = make_float2(o0, o1);
            }
            if (SC && warp < 2 && tig == 0) {
                if (SC == 1) {
                    atomicAdd(&g_small[OFF_NCNT + sdst[r]], 1.0f);
                    atomicAdd(&g_small[OFF_GCE + sb[r]], 1.0f);
                } else {
                    atomicAdd(&g_small[OFF_GCN + sb[r]], 1.0f);
                }
            }
        }
    }
}

// ---------------- node_in = [n1, e2n_mean, g1[batch]] (tf32-rounded) --------
__global__ __launch_bounds__(192) void build_node_in(const int* __restrict__ batch)
{
    int v = blockIdx.x;
    int t = threadIdx.x;
    int seg = t / 64, w = t % 64;
    float4 val;
    if (seg == 0) {
        val = ((const float4*)g_n1)[(size_t)v * 64 + w];
    } else if (seg == 1) {
        float inv = 1.0f / fmaxf(g_small[OFF_NCNT + v], 1.0f);
        float4 sv = ((const float4*)g_e2n)[(size_t)v * 64 + w];
        val = make_float4(rtf(sv.x * inv), rtf(sv.y * inv),
                          rtf(sv.z * inv), rtf(sv.w * inv));
    } else {
        int b = batch[v];
        val = ((const float4*)g_g1)[(size_t)b * 64 + w];
    }
    ((float4*)g_nin)[(size_t)v * 192 + t] = val;
}

// ---------------- glob_in = [n2g_mean, e2g_mean, g1] (tf32-rounded) ---------
__global__ __launch_bounds__(192) void build_glob_in()
{
    int gi = blockIdx.x;
    int t = threadIdx.x;
    int seg = t / 64, w = t % 64;
    float4 val;
    if (seg == 0) {
        float inv = 1.0f / fmaxf(g_small[OFF_GCN + gi], 1.0f);
        float4 sv = *(const float4*)&g_small[OFF_N2G + gi * 256 + w * 4];
        val = make_float4(rtf(sv.x * inv), rtf(sv.y * inv),
                          rtf(sv.z * inv), rtf(sv.w * inv));
    } else if (seg == 1) {
        float inv = 1.0f / fmaxf(g_small[OFF_GCE + gi], 1.0f);
        float4 sv = *(const float4*)&g_small[OFF_E2G + gi * 256 + w * 4];
        val = make_float4(rtf(sv.x * inv), rtf(sv.y * inv),
                          rtf(sv.z * inv), rtf(sv.w * inv));
    } else {
        val = ((const float4*)g_g1)[(size_t)gi * 64 + w];
    }
    ((float4*)g_gin)[(size_t)gi * 192 + t] = val;
}

// ---------------- host side ---------------------------------------------------
template <typename T>
static T* sym(const void* symbol) {
    void* p = nullptr;
    cudaGetSymbolAddress(&p, symbol);
    return (T*)p;
}

extern "C" void kernel_launch(void* const* d_in, const int* in_sizes, int n_in,
                              void* d_out, int out_size) {
    const float* node_feats = (const float*)d_in[0];
    const float* edge_feats = (const float*)d_in[1];
    const float* glob_feats = (const float*)d_in[2];
    const int*   edge_index = (const int*)d_in[3];
    const int*   batch      = (const int*)d_in[4];

    const int* src = edge_index;
    const int* dst = edge_index + NE;

    float* out = (float*)d_out;
    float* out_n = out;
    float* out_e = out + (size_t)NN * 256;
    float* out_g = out + (size_t)(NN + NE) * 256;

    float* p_n1   = sym<float>(g_n1);
    float* p_e1   = sym<float>(g_e1);
    float* p_g1   = sym<float>(g_g1);
    float* p_emid = sym<float>(g_emid);
    float* p_nin  = sym<float>(g_nin);
    float* p_nmid = sym<float>(g_nmid);
    float* p_gin  = sym<float>(g_gin);
    float* p_gmid = sym<float>(g_gmid);
    float* p_e2n  = sym<float>(g_e2n);
    float* p_small = sym<float>(g_small);
    float* p_wr   = sym<float>(g_wr);

    // zero scatter accumulators
    zero_kernel<<<(NN * 256 + 255) / 256, 256>>>(p_e2n, NN * 256);
    zero_kernel<<<(SMALL_N + 255) / 256, 256>>>(p_small, SMALL_N);

    // round weights once per call
    WSrc ws;
    for (int i = 0; i < 9; i++) ws.p[i] = (const float*)d_in[5 + i];
    round_weights<<<1024, 256>>>(ws);

    // stage 1: input projections + ssp (A raw fp32 -> HW tf32 truncation)
    gemm_k<0,0,1,0><<<(NN + 127) / 128, 256>>>(node_feats, p_wr + WO0,
        nullptr, p_n1, NN, 256, nullptr, nullptr, nullptr);
    gemm_k<0,0,1,0><<<(NE + 127) / 128, 256>>>(edge_feats, p_wr + WO1,
        nullptr, p_e1, NE, 256, nullptr, nullptr, nullptr);
    gemm_k<0,0,1,0><<<1, 256>>>(glob_feats, p_wr + WO2,
        nullptr, p_g1, NG, 256, nullptr, nullptr, nullptr);

    // EdgeModel: gather fused in, scatter (e2n/e2g/counts) fused out
    gemm_k<1,0,1,1><<<(NE + 127) / 128, 256>>>(nullptr, p_wr + WO3,
        nullptr, p_emid, NE, 1024, src, dst, batch);

    // NodeModel
    build_node_in<<<NN, 192>>>(batch);
    gemm_k<0,0,1,2><<<(NN + 127) / 128, 256>>>(p_nin, p_wr + WO4,
        nullptr, p_nmid, NN, 768, nullptr, nullptr, batch);

    // GlobalModel
    build_glob_in<<<NG, 192>>>();
    gemm_k<0,0,1,0><<<1, 256>>>(p_gin, p_wr + WO5,
        nullptr, p_gmid, NG, 768, nullptr, nullptr, nullptr);

    // output projections + ssp + residual (full-precision outputs)
    gemm_k<0,1,0,0><<<(NN + 127) / 128, 256>>>(p_nmid, p_wr + WO6,
        node_feats, out_n, NN, 256, nullptr, nullptr, nullptr);
    gemm_k<0,1,0,0><<<(NE + 127) / 128, 256>>>(p_emid, p_wr + WO7,
        edge_feats, out_e, NE, 256, nullptr, nullptr, nullptr);
    gemm_k<0,1,0,0><<<1, 256>>>(p_gmid, p_wr + WO8,
        glob_feats, out_g, NG, 256, nullptr, nullptr, nullptr);
}

// round 4
// speedup vs baseline: 1.1542x; 1.1542x over previous
#include <cuda_runtime.h>
#include <cstddef>
#include <cstdint>

#define NN 20000
#define NE 200000
#define NG 128

// ---------------- scratch (device globals) ----------------------------------
__device__ float g_n1[(size_t)NN * 256];
__device__ float g_e1[(size_t)NE * 256];
__device__ float g_g1[(size_t)NG * 256];
__device__ float g_emid[(size_t)NE * 256];
__device__ float g_nin[(size_t)NN * 768];
__device__ float g_nmid[(size_t)NN * 256];
__device__ float g_gin[(size_t)NG * 768];
__device__ float g_gmid[(size_t)NG * 256];
__device__ float g_e2n[(size_t)NN * 256];
#define OFF_E2G 0
#define OFF_N2G 32768
#define OFF_NCNT 65536
#define OFF_GCE 85536
#define OFF_GCN 85664
#define SMALL_N 85792
__device__ float g_small[SMALL_N];
__device__ float g_wr[1048576];   // all 9 weights, tf32-rounded

__device__ __forceinline__ float ssp(float x) {
    return fmaxf(x, 0.0f) + log1pf(__expf(-fabsf(x))) - 0.69314718055994531f;
}
__device__ __forceinline__ uint32_t f2tf32(float f) {
    uint32_t r;
    asm("cvt.rna.tf32.f32 %0, %1;" : "=r"(r) : "f"(f));
    return r;
}
__device__ __forceinline__ float rtf(float f) {
    return __uint_as_float(f2tf32(f));
}
__device__ __forceinline__ void mma_tf32(float* c,
    uint32_t a0, uint32_t a1, uint32_t a2, uint32_t a3,
    uint32_t b0, uint32_t b1)
{
    asm volatile(
        "mma.sync.aligned.m16n8k8.row.col.f32.tf32.tf32.f32 "
        "{%0,%1,%2,%3},{%4,%5,%6,%7},{%8,%9},{%0,%1,%2,%3};\n"
        : "+f"(c[0]), "+f"(c[1]), "+f"(c[2]), "+f"(c[3])
        : "r"(a0), "r"(a1), "r"(a2), "r"(a3), "r"(b0), "r"(b1));
}
__device__ __forceinline__ void cp16(uint32_t saddr, const void* g) {
    asm volatile("cp.async.cg.shared.global [%0], [%1], 16;\n"
                 :: "r"(saddr), "l"(g));
}
__device__ __forceinline__ void ldsm4(uint32_t& r0, uint32_t& r1,
                                      uint32_t& r2, uint32_t& r3, uint32_t a) {
    asm volatile("ldmatrix.sync.aligned.m8n8.x4.shared.b16 {%0,%1,%2,%3},[%4];\n"
                 : "=r"(r0), "=r"(r1), "=r"(r2), "=r"(r3) : "r"(a));
}

// ---------------- zero fill --------------------------------------------------
__global__ void zero_kernel(float* __restrict__ p, int n) {
    int i = blockIdx.x * blockDim.x + threadIdx.x;
    if (i < n) p[i] = 0.0f;
}

// ---------------- round all weights into g_wr --------------------------------
struct WSrc { const float* p[9]; };
#define WO0 0
#define WO1 65536
#define WO2 131072
#define WO3 196608
#define WO4 458752
#define WO5 655360
#define WO6 851968
#define WO7 917504
#define WO8 983040
__global__ __launch_bounds__(256) void round_weights(WSrc ws) {
    int f = (blockIdx.x * 256 + threadIdx.x) * 4;
    if (f >= 1048576) return;
    const float* sp; int base;
    if      (f < WO1) { sp = ws.p[0]; base = WO0; }
    else if (f < WO2) { sp = ws.p[1]; base = WO1; }
    else if (f < WO3) { sp = ws.p[2]; base = WO2; }
    else if (f < WO4) { sp = ws.p[3]; base = WO3; }
    else if (f < WO5) { sp = ws.p[4]; base = WO4; }
    else if (f < WO6) { sp = ws.p[5]; base = WO5; }
    else if (f < WO7) { sp = ws.p[6]; base = WO6; }
    else if (f < WO8) { sp = ws.p[7]; base = WO7; }
    else              { sp = ws.p[8]; base = WO8; }
    float4 v = *(const float4*)(sp + (f - base));
    v.x = rtf(v.x); v.y = rtf(v.y); v.z = rtf(v.z); v.w = rtf(v.w);
    *(float4*)(g_wr + f) = v;
}

// ---------------- main GEMM: C[M,256] = ssp(A @ W^T) variants ----------------
// Block 128x128xK (grid.x = 2 n-blocks). 8 warps, warp tile 32x64 (4m x 2n).
// ldmatrix.x4 fragments from XOR-swizzled smem, cp.async double buffer,
// 2 CTAs/SM. MODE1 = fused edge gather (K=1024). SC1 = edge scatter fused,
// SC2 = node scatter fused. ROUND = store tf32-rounded. ADD = +R residual.
// Stage: A[128x16] at 0, W[128x16] at 8192B; stage stride 16384B.

template <int MODE, int ADD, int ROUND, int SC>
__global__ __launch_bounds__(256, 2) void gemm_k(
    const float* __restrict__ A, const float* __restrict__ W,
    const float* __restrict__ R, float* __restrict__ C,
    int M, int K,
    const int* __restrict__ src, const int* __restrict__ dst,
    const int* __restrict__ batch)
{
    __shared__ __align__(1024) float sm[8192];
    const int tid = threadIdx.x;
    const int m0 = blockIdx.y * 128;
    const int n0 = blockIdx.x * 128;
    const uint32_t smb = (uint32_t)__cvta_generic_to_shared(sm);

    // ---- loader: threads 0-127 load A rows, 128-255 load W rows (1 row each)
    const int lrow = tid & 127;
    const int ls = (lrow >> 1) & 3;
    uint32_t st0, st1, st2, st3;
    {
        uint32_t base = smb + (uint32_t)(lrow * 64) + ((tid < 128) ? 0u : 8192u);
        st0 = base + (uint32_t)((0 ^ ls) << 4);
        st1 = base + (uint32_t)((1 ^ ls) << 4);
        st2 = base + (uint32_t)((2 ^ ls) << 4);
        st3 = base + (uint32_t)((3 ^ ls) << 4);
    }
    const float* gRow = nullptr;
    const float* gp0 = nullptr; const float* gp1 = nullptr;
    const float* gp2 = nullptr; const float* gp3 = nullptr;
    if (tid < 128) {
        if (MODE == 0) {
            int r = min(m0 + lrow, M - 1);
            gRow = A + (size_t)r * K;
        } else {
            int e = min(m0 + lrow, NE - 1);
            int s_ = src[e], d_ = dst[e], b_ = batch[s_];
            gp0 = g_n1 + (size_t)s_ * 256;
            gp1 = g_n1 + (size_t)d_ * 256;
            gp2 = g_e1 + (size_t)e * 256;
            gp3 = g_g1 + (size_t)b_ * 256;
        }
    } else {
        gRow = W + (size_t)(n0 + lrow) * K;
    }

    auto load_tile = [&](int kt, int stg) {
        uint32_t so = (uint32_t)stg * 16384u;
        const float* p;
        if (MODE == 1 && tid < 128) {
            int sg = kt >> 4;
            const float* b = (sg == 0) ? gp0 : (sg == 1) ? gp1
                           : (sg == 2) ? gp2 : gp3;
            p = b + (kt & 15) * 16;
        } else {
            p = gRow + kt * 16;
        }
        cp16(st0 + so, p);
        cp16(st1 + so, p + 4);
        cp16(st2 + so, p + 8);
        cp16(st3 + so, p + 12);
        asm volatile("cp.async.commit_group;\n" ::: "memory");
    };

    // ---- compute mapping: warp tile 32x64, warps (warp&3)=m, (warp>>2)=n
    const int lane = tid & 31, warp = tid >> 5;
    const int wm = (warp & 3) * 32;
    const int wn = (warp >> 2) * 64;
    const int gid = lane >> 2, tig = lane & 3;

    const int arow = wm + (lane & 15);
    const uint32_t aBase = smb + (uint32_t)(arow * 64)
                         + ((((uint32_t)arow >> 1) & 3u) << 4);
    const uint32_t hA = (uint32_t)((lane >> 4) & 1) << 4;
    const int brow = wn + ((lane >> 4) & 1) * 8 + (lane & 7);
    const uint32_t bBase = smb + 8192u + (uint32_t)(brow * 64)
                         + ((((uint32_t)brow >> 1) & 3u) << 4);
    const uint32_t hB = (uint32_t)((lane >> 3) & 1) << 4;

    float acc[2][8][4];
#pragma unroll
    for (int mt = 0; mt < 2; mt++)
#pragma unroll
        for (int nt = 0; nt < 8; nt++)
#pragma unroll
            for (int i = 0; i < 4; i++) acc[mt][nt][i] = 0.0f;

    const int KT = K / 16;
    load_tile(0, 0);

    for (int kt = 0; kt < KT; kt++) {
        asm volatile("cp.async.wait_group 0;\n" ::: "memory");
        __syncthreads();
        if (kt + 1 < KT) load_tile(kt + 1, (kt + 1) & 1);
        const uint32_t so = (uint32_t)(kt & 1) * 16384u;

#pragma unroll
        for (int ks = 0; ks < 2; ks++) {
            const uint32_t kxA = ((uint32_t)(ks << 5)) | hA;
            const uint32_t kxB = ((uint32_t)(ks << 5)) | hB;
            uint32_t a[2][4];
#pragma unroll
            for (int mt = 0; mt < 2; mt++)
                ldsm4(a[mt][0], a[mt][1], a[mt][2], a[mt][3],
                      (aBase + so + (uint32_t)(mt * 1024)) ^ kxA);
            uint32_t b0[8], b1[8];
#pragma unroll
            for (int g = 0; g < 4; g++)
                ldsm4(b0[2 * g], b1[2 * g], b0[2 * g + 1], b1[2 * g + 1],
                      (bBase + so + (uint32_t)(g * 1024)) ^ kxB);
#pragma unroll
            for (int mt = 0; mt < 2; mt++)
#pragma unroll
                for (int nt = 0; nt < 8; nt++)
                    mma_tf32(acc[mt][nt], a[mt][0], a[mt][1], a[mt][2],
                             a[mt][3], b0[nt], b1[nt]);
        }
        __syncthreads();
    }

    // ---- epilogue
    int* sdst = (int*)sm;
    int* sbt = ((int*)sm) + 128;
    if (SC) {
        if (tid < 128) {
            int e = min(m0 + tid, M - 1);
            if (SC == 1) { sdst[tid] = dst[e]; sbt[tid] = batch[src[e]]; }
            else sbt[tid] = batch[e];
        }
        __syncthreads();
    }

#pragma unroll
    for (int mt = 0; mt < 2; mt++) {
#pragma unroll
        for (int half = 0; half < 2; half++) {
            int r = wm + mt * 16 + half * 8 + gid;
            int gr = m0 + r;
            if (gr >= M) continue;
#pragma unroll
            for (int nt = 0; nt < 8; nt++) {
                int col = n0 + wn + nt * 8 + tig * 2;
                float o0 = ssp(acc[mt][nt][half * 2 + 0]);
                float o1 = ssp(acc[mt][nt][half * 2 + 1]);
                if (SC == 1) {
                    atomicAdd(&g_e2n[(size_t)sdst[r] * 256 + col], o0);
                    atomicAdd(&g_e2n[(size_t)sdst[r] * 256 + col + 1], o1);
                    atomicAdd(&g_small[OFF_E2G + sbt[r] * 256 + col], o0);
                    atomicAdd(&g_small[OFF_E2G + sbt[r] * 256 + col + 1], o1);
                } else if (SC == 2) {
                    atomicAdd(&g_small[OFF_N2G + sbt[r] * 256 + col], o0);
                    atomicAdd(&g_small[OFF_N2G + sbt[r] * 256 + col + 1], o1);
                }
                if (ADD) {
                    float2 rv = *(const float2*)&R[(size_t)gr * 256 + col];
                    o0 += rv.x; o1 += rv.y;
                }
                if (ROUND) { o0 = rtf(o0); o1 = rtf(o1); }
                *(float2*)&C[(size_t)gr * 256 + col] = make_float2(o0, o1);
            }
            if (SC && blockIdx.x == 0 && wn == 0 && tig == 0) {
                if (SC == 1) {
                    atomicAdd(&g_small[OFF_NCNT + sdst[r]], 1.0f);
                    atomicAdd(&g_small[OFF_GCE + sbt[r]], 1.0f);
                } else {
                    atomicAdd(&g_small[OFF_GCN + sbt[r]], 1.0f);
                }
            }
        }
    }
}

// ---------------- node_in = [n1, e2n_mean, g1[batch]] (tf32-rounded) --------
__global__ __launch_bounds__(192) void build_node_in(const int* __restrict__ batch)
{
    int v = blockIdx.x;
    int t = threadIdx.x;
    int seg = t / 64, w = t % 64;
    float4 val;
    if (seg == 0) {
        val = ((const float4*)g_n1)[(size_t)v * 64 + w];
    } else if (seg == 1) {
        float inv = 1.0f / fmaxf(g_small[OFF_NCNT + v], 1.0f);
        float4 sv = ((const float4*)g_e2n)[(size_t)v * 64 + w];
        val = make_float4(rtf(sv.x * inv), rtf(sv.y * inv),
                          rtf(sv.z * inv), rtf(sv.w * inv));
    } else {
        int b = batch[v];
        val = ((const float4*)g_g1)[(size_t)b * 64 + w];
    }
    ((float4*)g_nin)[(size_t)v * 192 + t] = val;
}

// ---------------- glob_in = [n2g_mean, e2g_mean, g1] (tf32-rounded) ---------
__global__ __launch_bounds__(192) void build_glob_in()
{
    int gi = blockIdx.x;
    int t = threadIdx.x;
    int seg = t / 64, w = t % 64;
    float4 val;
    if (seg == 0) {
        float inv = 1.0f / fmaxf(g_small[OFF_GCN + gi], 1.0f);
        float4 sv = *(const float4*)&g_small[OFF_N2G + gi * 256 + w * 4];
        val = make_float4(rtf(sv.x * inv), rtf(sv.y * inv),
                          rtf(sv.z * inv), rtf(sv.w * inv));
    } else if (seg == 1) {
        float inv = 1.0f / fmaxf(g_small[OFF_GCE + gi], 1.0f);
        float4 sv = *(const float4*)&g_small[OFF_E2G + gi * 256 + w * 4];
        val = make_float4(rtf(sv.x * inv), rtf(sv.y * inv),
                          rtf(sv.z * inv), rtf(sv.w * inv));
    } else {
        val = ((const float4*)g_g1)[(size_t)gi * 64 + w];
    }
    ((float4*)g_gin)[(size_t)gi * 192 + t] = val;
}

// ---------------- host side ---------------------------------------------------
template <typename T>
static T* sym(const void* symbol) {
    void* p = nullptr;
    cudaGetSymbolAddress(&p, symbol);
    return (T*)p;
}

extern "C" void kernel_launch(void* const* d_in, const int* in_sizes, int n_in,
                              void* d_out, int out_size) {
    const float* node_feats = (const float*)d_in[0];
    const float* edge_feats = (const float*)d_in[1];
    const float* glob_feats = (const float*)d_in[2];
    const int*   edge_index = (const int*)d_in[3];
    const int*   batch      = (const int*)d_in[4];

    const int* src = edge_index;
    const int* dst = edge_index + NE;

    float* out = (float*)d_out;
    float* out_n = out;
    float* out_e = out + (size_t)NN * 256;
    float* out_g = out + (size_t)(NN + NE) * 256;

    float* p_n1   = sym<float>(g_n1);
    float* p_e1   = sym<float>(g_e1);
    float* p_g1   = sym<float>(g_g1);
    float* p_emid = sym<float>(g_emid);
    float* p_nin  = sym<float>(g_nin);
    float* p_nmid = sym<float>(g_nmid);
    float* p_gin  = sym<float>(g_gin);
    float* p_gmid = sym<float>(g_gmid);
    float* p_e2n  = sym<float>(g_e2n);
    float* p_small = sym<float>(g_small);
    float* p_wr   = sym<float>(g_wr);

    // zero scatter accumulators
    zero_kernel<<<(NN * 256 + 255) / 256, 256>>>(p_e2n, NN * 256);
    zero_kernel<<<(SMALL_N + 255) / 256, 256>>>(p_small, SMALL_N);

    // round weights once per call
    WSrc ws;
    for (int i = 0; i < 9; i++) ws.p[i] = (const float*)d_in[5 + i];
    round_weights<<<1024, 256>>>(ws);

    // stage 1: input projections + ssp
    gemm_k<0,0,1,0><<<dim3(2, (NN + 127) / 128), 256>>>(node_feats, p_wr + WO0,
        nullptr, p_n1, NN, 256, nullptr, nullptr, nullptr);
    gemm_k<0,0,1,0><<<dim3(2, (NE + 127) / 128), 256>>>(edge_feats, p_wr + WO1,
        nullptr, p_e1, NE, 256, nullptr, nullptr, nullptr);
    gemm_k<0,0,1,0><<<dim3(2, 1), 256>>>(glob_feats, p_wr + WO2,
        nullptr, p_g1, NG, 256, nullptr, nullptr, nullptr);

    // EdgeModel: gather fused in, scatter (e2n/e2g/counts) fused out
    gemm_k<1,0,1,1><<<dim3(2, (NE + 127) / 128), 256>>>(nullptr, p_wr + WO3,
        nullptr, p_emid, NE, 1024, src, dst, batch);

    // NodeModel
    build_node_in<<<NN, 192>>>(batch);
    gemm_k<0,0,1,2><<<dim3(2, (NN + 127) / 128), 256>>>(p_nin, p_wr + WO4,
        nullptr, p_nmid, NN, 768, nullptr, nullptr, batch);

    // GlobalModel
    build_glob_in<<<NG, 192>>>();
    gemm_k<0,0,1,0><<<dim3(2, 1), 256>>>(p_gin, p_wr + WO5,
        nullptr, p_gmid, NG, 768, nullptr, nullptr, nullptr);

    // output projections + ssp + residual (full-precision outputs)
    gemm_k<0,1,0,0><<<dim3(2, (NN + 127) / 128), 256>>>(p_nmid, p_wr + WO6,
        node_feats, out_n, NN, 256, nullptr, nullptr, nullptr);
    gemm_k<0,1,0,0><<<dim3(2, (NE + 127) / 128), 256>>>(p_emid, p_wr + WO7,
        edge_feats, out_e, NE, 256, nullptr, nullptr, nullptr);
    gemm_k<0,1,0,0><<<dim3(2, 1), 256>>>(p_gmid, p_wr + WO8,
        glob_feats, out_g, NG, 256, nullptr, nullptr, nullptr);
}